// round 5
// baseline (speedup 1.0000x reference)
#include <cuda_runtime.h>
#include <math.h>

// Problem constants (fixed by the dataset)
#define T_TYPES 4
#define U_DIM   10
#define U_PAD   12                     // padded so each (s,t) row is 48B, 16B-aligned
#define EMB     200
#define DIM_A   20
#define TUP     (T_TYPES * U_PAD)      // 48 floats per node
#define MAX_NSRC 65536
#define MAX_NDST 8192
#define NSLICE  7                      // ceil(EMB/32)
#define ROWS_PB 8                      // rows per project block

// Scratch (device globals: allocation-free)
__device__ float g_src_feat[MAX_NSRC * TUP];  // [s][t*U_PAD+u], 12.6 MB
__device__ float g_agg[MAX_NDST * TUP];       // [b][t*U_PAD+u], 1.6 MB
__device__ float g_comb[MAX_NDST * U_DIM];    // [b][u]

// ---------------------------------------------------------------------------
// K1: gather node_type_embeddings rows into compact padded buffer
//     (also zeroes g_agg: disjoint buffer, rides along for free)
// ---------------------------------------------------------------------------
__global__ void gather_kernel(const int* __restrict__ input_nodes,
                              const float* __restrict__ nte_table,
                              int n_src, int n_zero4) {
    int i = blockIdx.x * blockDim.x + threadIdx.x;
    if (i < n_zero4)
        reinterpret_cast<float4*>(g_agg)[i] = make_float4(0.f, 0.f, 0.f, 0.f);
    int total = n_src * T_TYPES;
    if (i >= total) return;
    int s = i >> 2;
    int t = i & 3;
    int node = __ldg(&input_nodes[s]);
    const float2* src = reinterpret_cast<const float2*>(
        nte_table + (size_t)node * (T_TYPES * U_DIM) + t * U_DIM);
    float2* dst = reinterpret_cast<float2*>(
        g_src_feat + (size_t)s * TUP + t * U_PAD);
#pragma unroll
    for (int q = 0; q < 5; q++) dst[q] = __ldg(&src[q]);
    dst[5] = make_float2(0.0f, 0.0f);   // padding
}

// ---------------------------------------------------------------------------
// K2: per-edge scatter-add using vectorized global reductions (sm_90+)
// ---------------------------------------------------------------------------
__device__ __forceinline__ void red_v4(float* p, float4 v) {
    asm volatile("red.global.add.v4.f32 [%0], {%1, %2, %3, %4};"
                 :: "l"(p), "f"(v.x), "f"(v.y), "f"(v.z), "f"(v.w)
                 : "memory");
}
__device__ __forceinline__ void red_v2(float* p, float2 v) {
    asm volatile("red.global.add.v2.f32 [%0], {%1, %2};"
                 :: "l"(p), "f"(v.x), "f"(v.y)
                 : "memory");
}

__global__ void edge_kernel(const int* __restrict__ edge_src,
                            const int* __restrict__ edge_dst,
                            int E) {
    int idx = blockIdx.x * blockDim.x + threadIdx.x;
    int total = T_TYPES * E;
    if (idx >= total) return;
    int t = idx / E;
    int e = idx - t * E;
    int s = __ldg(&edge_src[(size_t)t * E + e]);
    int d = __ldg(&edge_dst[(size_t)t * E + e]);
    const float* src = g_src_feat + (size_t)s * TUP + t * U_PAD;   // 16B-aligned
    float*       dst = g_agg      + (size_t)d * TUP + t * U_PAD;   // 16B-aligned
    float4 a = __ldg(reinterpret_cast<const float4*>(src));
    float4 b = __ldg(reinterpret_cast<const float4*>(src + 4));
    float2 c = __ldg(reinterpret_cast<const float2*>(src + 8));
    red_v4(dst, a);
    red_v4(dst + 4, b);
    red_v2(dst + 8, c);
}

// ---------------------------------------------------------------------------
// K3a: attention + combine.  FOUR lanes per dst node (lane&3 == t).
// ---------------------------------------------------------------------------
__global__ void __launch_bounds__(256)
combine_kernel(const float* __restrict__ s1,    // [T,U,A]
               const float* __restrict__ s2,    // [T,A,1]
               int n_dst)
{
    __shared__ float s1_s[T_TYPES * U_DIM * DIM_A];   // 800 floats
    __shared__ float s2_s[T_TYPES * DIM_A];           // 80 floats

    int tid = threadIdx.x;
    for (int i = tid; i < T_TYPES * U_DIM * DIM_A; i += 256) s1_s[i] = __ldg(&s1[i]);
    if (tid < T_TYPES * DIM_A) s2_s[tid] = __ldg(&s2[tid]);
    __syncthreads();

    int gidx = blockIdx.x * blockDim.x + tid;
    int j = gidx >> 2;          // node
    int t = gidx & 3;           // edge type (lane&3 == t since blockDim%4==0)
    if (j >= n_dst) return;

    // load this lane's nte[t] row: 3 x float4 (48B aligned)
    float nte[12];
    {
        const float4* p = reinterpret_cast<const float4*>(
            g_agg + (size_t)j * TUP + t * U_PAD);
#pragma unroll
        for (int q = 0; q < 3; q++) {
            float4 v = p[q];
            nte[4 * q] = v.x; nte[4 * q + 1] = v.y;
            nte[4 * q + 2] = v.z; nte[4 * q + 3] = v.w;
        }
    }

    float score = 0.0f;
#pragma unroll
    for (int a = 0; a < DIM_A; a++) {
        float h = 0.0f;
#pragma unroll
        for (int u = 0; u < U_DIM; u++)
            h += nte[u] * s1_s[(t * U_DIM + u) * DIM_A + a];
        score += tanhf(h) * s2_s[t * DIM_A + a];
    }

    // softmax across the 4 lanes of this node
    float m = score;
    m = fmaxf(m, __shfl_xor_sync(0xffffffffu, m, 1));
    m = fmaxf(m, __shfl_xor_sync(0xffffffffu, m, 2));
    float ex = expf(score - m);
    float sum = ex;
    sum += __shfl_xor_sync(0xffffffffu, sum, 1);
    sum += __shfl_xor_sync(0xffffffffu, sum, 2);
    float att = ex / sum;

    // comb[u] = sum_t att[t] * nte[t][u]  (reduce across the 4 lanes)
    float comb[U_DIM];
#pragma unroll
    for (int u = 0; u < U_DIM; u++) {
        float v = att * nte[u];
        v += __shfl_xor_sync(0xffffffffu, v, 1);
        v += __shfl_xor_sync(0xffffffffu, v, 2);
        comb[u] = v;
    }
    if (t == 0) {
        float2* o = reinterpret_cast<float2*>(g_comb + (size_t)j * U_DIM);
#pragma unroll
        for (int q = 0; q < 5; q++)
            o[q] = make_float2(comb[2 * q], comb[2 * q + 1]);
    }
}

// ---------------------------------------------------------------------------
// K3b: projection + normalize.  Block = 128 threads (4 warps), fixed t,
//      ROWS_PB rows.  Warp w owns e-slices {w, w+4} -> Wr is only 20 regs.
//      Cross-warp ssq via smem, ONE __syncthreads per block.
// ---------------------------------------------------------------------------
__global__ void __launch_bounds__(128)
project_kernel(const int*   __restrict__ output_nodes,
               const float* __restrict__ node_emb,
               const float* __restrict__ W,      // [T,U,EMB]
               float* __restrict__ out,          // [B,T,EMB]
               int n_dst)
{
    int t    = blockIdx.y;
    int lane = threadIdx.x & 31;
    int w    = threadIdx.x >> 5;          // 4 warps
    int b0   = blockIdx.x * ROWS_PB;

    int eA = w * 32 + lane;               // slice w      (always < 128 < EMB)
    int eB = (w + 4) * 32 + lane;         // slice w+4    (may be >= EMB)
    bool hasB = (eB < EMB);

    // W registers: 2 slices x 10 u = 20 regs
    float WrA[U_DIM], WrB[U_DIM];
#pragma unroll
    for (int u = 0; u < U_DIM; u++) {
        WrA[u] = __ldg(&W[(size_t)(t * U_DIM + u) * EMB + eA]);
        WrB[u] = hasB ? __ldg(&W[(size_t)(t * U_DIM + u) * EMB + eB]) : 0.0f;
    }

    __shared__ float ssq_s[ROWS_PB][4];
    float vA[ROWS_PB], vB[ROWS_PB];

    // phase 1: compute values + per-warp partial ssq for all rows
#pragma unroll
    for (int r = 0; r < ROWS_PB; r++) {
        int b = b0 + r;
        float valA = 0.0f, valB = 0.0f;
        if (b < n_dst) {
            float c[U_DIM];
#pragma unroll
            for (int u = 0; u < U_DIM; u++)
                c[u] = __ldg(&g_comb[(size_t)b * U_DIM + u]);   // broadcast

            int node = __ldg(&output_nodes[b]);
            const float* base = node_emb + (size_t)node * EMB;
            valA = __ldg(&base[eA]);
            valB = hasB ? __ldg(&base[eB]) : 0.0f;
#pragma unroll
            for (int u = 0; u < U_DIM; u++) {
                valA += c[u] * WrA[u];
                valB += c[u] * WrB[u];
            }
            if (!hasB) valB = 0.0f;
        }
        vA[r] = valA;
        vB[r] = valB;
        float ssq = valA * valA + valB * valB;
#pragma unroll
        for (int off = 16; off > 0; off >>= 1)
            ssq += __shfl_xor_sync(0xffffffffu, ssq, off);
        if (lane == 0) ssq_s[r][w] = ssq;
    }
    __syncthreads();

    // phase 2: total ssq, normalize, store
#pragma unroll
    for (int r = 0; r < ROWS_PB; r++) {
        int b = b0 + r;
        if (b >= n_dst) continue;
        float tot = ssq_s[r][0] + ssq_s[r][1] + ssq_s[r][2] + ssq_s[r][3];
        float inv = 1.0f / fmaxf(sqrtf(tot), 1e-12f);
        float* o = out + ((size_t)b * T_TYPES + t) * EMB;
        o[eA] = vA[r] * inv;
        if (hasB) o[eB] = vB[r] * inv;
    }
}

// ---------------------------------------------------------------------------
// Launch
// ---------------------------------------------------------------------------
extern "C" void kernel_launch(void* const* d_in, const int* in_sizes, int n_in,
                              void* d_out, int out_size) {
    const int*   input_nodes  = (const int*)  d_in[0];
    const int*   output_nodes = (const int*)  d_in[1];
    const int*   edge_src     = (const int*)  d_in[2];
    const int*   edge_dst     = (const int*)  d_in[3];
    const float* node_emb     = (const float*)d_in[4];
    const float* nte_table    = (const float*)d_in[5];
    const float* W            = (const float*)d_in[6];
    const float* s1           = (const float*)d_in[7];
    const float* s2           = (const float*)d_in[8];
    float* out = (float*)d_out;

    int n_src = in_sizes[0];
    int n_dst = in_sizes[1];
    int E     = in_sizes[2] / T_TYPES;

    // K1: gather (one thread per (s,t)) + zero agg
    {
        int n_zero4 = (n_dst * TUP) / 4;
        int n = n_src * T_TYPES;
        int nthreads = n > n_zero4 ? n : n_zero4;
        gather_kernel<<<(nthreads + 255) / 256, 256>>>(input_nodes, nte_table,
                                                       n_src, n_zero4);
    }
    // K2: scatter-add over edges (vector reds)
    {
        int n = T_TYPES * E;
        edge_kernel<<<(n + 255) / 256, 256>>>(edge_src, edge_dst, E);
    }
    // K3a: attention + combine (4 lanes per node)
    {
        int n = n_dst * T_TYPES;
        combine_kernel<<<(n + 255) / 256, 256>>>(s1, s2, n_dst);
    }
    // K3b: projection + normalize (4-warp split per row group)
    {
        dim3 grid((n_dst + ROWS_PB - 1) / ROWS_PB, T_TYPES);
        project_kernel<<<grid, 128>>>(output_nodes, node_emb, W, out, n_dst);
    }
}

// round 6
// speedup vs baseline: 1.0808x; 1.0808x over previous
#include <cuda_runtime.h>
#include <math.h>

// Problem constants (fixed by the dataset)
#define T_TYPES 4
#define U_DIM   10
#define U_PAD   12                     // padded so each (s,t) row is 48B, 16B-aligned
#define EMB     200
#define DIM_A   20
#define TUP     (T_TYPES * U_PAD)      // 48 floats per node
#define MAX_NSRC 65536
#define MAX_NDST 8192
#define NSLICE  7                      // ceil(EMB/32)
#define ROWS_PW 8                      // rows per warp in project

// Scratch (device globals: allocation-free)
__device__ float g_src_feat[MAX_NSRC * TUP];  // [s][t*U_PAD+u], 12.6 MB
__device__ float g_agg[MAX_NDST * TUP];       // [b][t*U_PAD+u], 1.6 MB
__device__ float g_comb[MAX_NDST * U_DIM];    // [b][u]

// ---------------------------------------------------------------------------
// K1: gather node_type_embeddings rows into compact padded buffer
//     (also zeroes g_agg: disjoint buffer, rides along for free)
// ---------------------------------------------------------------------------
__global__ void gather_kernel(const int* __restrict__ input_nodes,
                              const float* __restrict__ nte_table,
                              int n_src, int n_zero4) {
    int i = blockIdx.x * blockDim.x + threadIdx.x;
    if (i < n_zero4)
        reinterpret_cast<float4*>(g_agg)[i] = make_float4(0.f, 0.f, 0.f, 0.f);
    int total = n_src * T_TYPES;
    if (i >= total) return;
    int s = i >> 2;
    int t = i & 3;
    int node = __ldg(&input_nodes[s]);
    const float2* src = reinterpret_cast<const float2*>(
        nte_table + (size_t)node * (T_TYPES * U_DIM) + t * U_DIM);
    float2* dst = reinterpret_cast<float2*>(
        g_src_feat + (size_t)s * TUP + t * U_PAD);
#pragma unroll
    for (int q = 0; q < 5; q++) dst[q] = __ldg(&src[q]);
    dst[5] = make_float2(0.0f, 0.0f);   // padding
}

// ---------------------------------------------------------------------------
// K2: per-edge scatter-add using vectorized global reductions (sm_90+)
// ---------------------------------------------------------------------------
__device__ __forceinline__ void red_v4(float* p, float4 v) {
    asm volatile("red.global.add.v4.f32 [%0], {%1, %2, %3, %4};"
                 :: "l"(p), "f"(v.x), "f"(v.y), "f"(v.z), "f"(v.w)
                 : "memory");
}
__device__ __forceinline__ void red_v2(float* p, float2 v) {
    asm volatile("red.global.add.v2.f32 [%0], {%1, %2};"
                 :: "l"(p), "f"(v.x), "f"(v.y)
                 : "memory");
}

__global__ void edge_kernel(const int* __restrict__ edge_src,
                            const int* __restrict__ edge_dst,
                            int E) {
    int idx = blockIdx.x * blockDim.x + threadIdx.x;
    int total = T_TYPES * E;
    if (idx >= total) return;
    int t = idx / E;
    int e = idx - t * E;
    int s = __ldg(&edge_src[(size_t)t * E + e]);
    int d = __ldg(&edge_dst[(size_t)t * E + e]);
    const float* src = g_src_feat + (size_t)s * TUP + t * U_PAD;   // 16B-aligned
    float*       dst = g_agg      + (size_t)d * TUP + t * U_PAD;   // 16B-aligned
    float4 a = __ldg(reinterpret_cast<const float4*>(src));
    float4 b = __ldg(reinterpret_cast<const float4*>(src + 4));
    float2 c = __ldg(reinterpret_cast<const float2*>(src + 8));
    red_v4(dst, a);
    red_v4(dst + 4, b);
    red_v2(dst + 8, c);
}

// ---------------------------------------------------------------------------
// K3a: attention + combine.  FOUR lanes per dst node (lane&3 == t).
// ---------------------------------------------------------------------------
__global__ void __launch_bounds__(256)
combine_kernel(const float* __restrict__ s1,    // [T,U,A]
               const float* __restrict__ s2,    // [T,A,1]
               int n_dst)
{
    __shared__ float s1_s[T_TYPES * U_DIM * DIM_A];   // 800 floats
    __shared__ float s2_s[T_TYPES * DIM_A];           // 80 floats

    int tid = threadIdx.x;
    for (int i = tid; i < T_TYPES * U_DIM * DIM_A; i += 256) s1_s[i] = __ldg(&s1[i]);
    if (tid < T_TYPES * DIM_A) s2_s[tid] = __ldg(&s2[tid]);
    __syncthreads();

    int gidx = blockIdx.x * blockDim.x + tid;
    int j = gidx >> 2;          // node
    int t = gidx & 3;           // edge type (lane&3 == t since blockDim%4==0)
    if (j >= n_dst) return;

    // load this lane's nte[t] row: 3 x float4 (48B aligned)
    float nte[12];
    {
        const float4* p = reinterpret_cast<const float4*>(
            g_agg + (size_t)j * TUP + t * U_PAD);
#pragma unroll
        for (int q = 0; q < 3; q++) {
            float4 v = p[q];
            nte[4 * q] = v.x; nte[4 * q + 1] = v.y;
            nte[4 * q + 2] = v.z; nte[4 * q + 3] = v.w;
        }
    }

    float score = 0.0f;
#pragma unroll
    for (int a = 0; a < DIM_A; a++) {
        float h = 0.0f;
#pragma unroll
        for (int u = 0; u < U_DIM; u++)
            h += nte[u] * s1_s[(t * U_DIM + u) * DIM_A + a];
        score += tanhf(h) * s2_s[t * DIM_A + a];
    }

    // softmax across the 4 lanes of this node
    float m = score;
    m = fmaxf(m, __shfl_xor_sync(0xffffffffu, m, 1));
    m = fmaxf(m, __shfl_xor_sync(0xffffffffu, m, 2));
    float ex = expf(score - m);
    float sum = ex;
    sum += __shfl_xor_sync(0xffffffffu, sum, 1);
    sum += __shfl_xor_sync(0xffffffffu, sum, 2);
    float att = ex / sum;

    // comb[u] = sum_t att[t] * nte[t][u]  (reduce across the 4 lanes)
    float comb[U_DIM];
#pragma unroll
    for (int u = 0; u < U_DIM; u++) {
        float v = att * nte[u];
        v += __shfl_xor_sync(0xffffffffu, v, 1);
        v += __shfl_xor_sync(0xffffffffu, v, 2);
        comb[u] = v;
    }
    if (t == 0) {
        float2* o = reinterpret_cast<float2*>(g_comb + (size_t)j * U_DIM);
#pragma unroll
        for (int q = 0; q < 5; q++)
            o[q] = make_float2(comb[2 * q], comb[2 * q + 1]);
    }
}

// ---------------------------------------------------------------------------
// K3b: projection + normalize.  One warp owns full rows (W[t] in 70 regs),
//      8 rows per warp, software-pipelined base/comb loads (double buffer).
// ---------------------------------------------------------------------------
__global__ void __launch_bounds__(128)
project_kernel(const int*   __restrict__ output_nodes,
               const float* __restrict__ node_emb,
               const float* __restrict__ W,      // [T,U,EMB]
               float* __restrict__ out,          // [B,T,EMB]
               int n_dst)
{
    int t    = blockIdx.y;
    int lane = threadIdx.x & 31;
    int w    = threadIdx.x >> 5;                    // 4 warps
    int b0   = blockIdx.x * (4 * ROWS_PW) + w * ROWS_PW;

    // W registers for this t: Wr[it][u] = W[t][u][it*32+lane]
    float Wr[NSLICE][U_DIM];
#pragma unroll
    for (int it = 0; it < NSLICE; it++) {
        int e = it * 32 + lane;
#pragma unroll
        for (int u = 0; u < U_DIM; u++)
            Wr[it][u] = (e < EMB) ? __ldg(&W[(size_t)(t * U_DIM + u) * EMB + e]) : 0.0f;
    }

    float c[2][U_DIM];
    float v[2][NSLICE];

    // preload row 0 (v starts as base)
    if (b0 < n_dst) {
        int node = __ldg(&output_nodes[b0]);
        const float* base = node_emb + (size_t)node * EMB;
#pragma unroll
        for (int it = 0; it < NSLICE; it++) {
            int e = it * 32 + lane;
            v[0][it] = (e < EMB) ? __ldg(&base[e]) : 0.0f;
        }
#pragma unroll
        for (int u = 0; u < U_DIM; u++)
            c[0][u] = __ldg(&g_comb[(size_t)b0 * U_DIM + u]);
    }

#pragma unroll
    for (int r = 0; r < ROWS_PW; r++) {
        const int cur = r & 1, nxt = cur ^ 1;

        // prefetch row r+1 (issued before compute so LDGs overlap FFMAs)
        if (r < ROWS_PW - 1) {
            int bn = b0 + r + 1;
            if (bn < n_dst) {
                int node = __ldg(&output_nodes[bn]);
                const float* base = node_emb + (size_t)node * EMB;
#pragma unroll
                for (int it = 0; it < NSLICE; it++) {
                    int e = it * 32 + lane;
                    v[nxt][it] = (e < EMB) ? __ldg(&base[e]) : 0.0f;
                }
#pragma unroll
                for (int u = 0; u < U_DIM; u++)
                    c[nxt][u] = __ldg(&g_comb[(size_t)bn * U_DIM + u]);
            }
        }

        int b = b0 + r;
        if (b < n_dst) {
            float ssq = 0.0f;
#pragma unroll
            for (int it = 0; it < NSLICE; it++) {
                float val = v[cur][it];
#pragma unroll
                for (int u = 0; u < U_DIM; u++)
                    val += c[cur][u] * Wr[it][u];
                v[cur][it] = val;
                ssq += val * val;
            }
#pragma unroll
            for (int off = 16; off > 0; off >>= 1)
                ssq += __shfl_xor_sync(0xffffffffu, ssq, off);
            float inv = 1.0f / fmaxf(sqrtf(ssq), 1e-12f);

            float* o = out + ((size_t)b * T_TYPES + t) * EMB;
#pragma unroll
            for (int it = 0; it < NSLICE; it++) {
                int e = it * 32 + lane;
                if (e < EMB) o[e] = v[cur][it] * inv;
            }
        }
    }
}

// ---------------------------------------------------------------------------
// Launch
// ---------------------------------------------------------------------------
extern "C" void kernel_launch(void* const* d_in, const int* in_sizes, int n_in,
                              void* d_out, int out_size) {
    const int*   input_nodes  = (const int*)  d_in[0];
    const int*   output_nodes = (const int*)  d_in[1];
    const int*   edge_src     = (const int*)  d_in[2];
    const int*   edge_dst     = (const int*)  d_in[3];
    const float* node_emb     = (const float*)d_in[4];
    const float* nte_table    = (const float*)d_in[5];
    const float* W            = (const float*)d_in[6];
    const float* s1           = (const float*)d_in[7];
    const float* s2           = (const float*)d_in[8];
    float* out = (float*)d_out;

    int n_src = in_sizes[0];
    int n_dst = in_sizes[1];
    int E     = in_sizes[2] / T_TYPES;

    // K1: gather (one thread per (s,t)) + zero agg
    {
        int n_zero4 = (n_dst * TUP) / 4;
        int n = n_src * T_TYPES;
        int nthreads = n > n_zero4 ? n : n_zero4;
        gather_kernel<<<(nthreads + 255) / 256, 256>>>(input_nodes, nte_table,
                                                       n_src, n_zero4);
    }
    // K2: scatter-add over edges (vector reds)
    {
        int n = T_TYPES * E;
        edge_kernel<<<(n + 255) / 256, 256>>>(edge_src, edge_dst, E);
    }
    // K3a: attention + combine (4 lanes per node)
    {
        int n = n_dst * T_TYPES;
        combine_kernel<<<(n + 255) / 256, 256>>>(s1, s2, n_dst);
    }
    // K3b: projection + normalize (warp-per-row, pipelined, 8 rows/warp)
    {
        int rows_per_block = 4 * ROWS_PW;   // 32
        dim3 grid((n_dst + rows_per_block - 1) / rows_per_block, T_TYPES);
        project_kernel<<<grid, 128>>>(output_nodes, node_emb, W, out, n_dst);
    }
}